// round 3
// baseline (speedup 1.0000x reference)
#include <cuda_runtime.h>
#include <cuda_bf16.h>

// B=4,C=128,H=W=64,L=4096, D=64, DI=128, N=16, R=4, K=4. bb=branch*4+b (8), bbk=bb*4+k (32)

__device__ float g_xd  [4*128*4096];
__device__ float g_xln [8*4096*64];
__device__ float g_xc  [8*4096*128];
__device__ float g_z   [8*4096*128];
__device__ float g_xc2 [8*4096*128];
__device__ float g_u   [32*4096*128];
__device__ float g_dbl [32*4096*36];
__device__ float g_del [32*4096*128];
__device__ float g_y4  [32*4096*128];
__device__ float g_g   [8*4096*128];
__device__ float g_xo  [4*128*4096];

__device__ __forceinline__ int pos_map(int k, int t){
    int tt = (k >= 2) ? (4095 - t) : t;
    if (k & 1) tt = ((tt & 63) << 6) | (tt >> 6);
    return tt;
}

// K1: depthwise 3x3 on input x (NCHW), 512 planes
__global__ void k1_dwconv(const float* __restrict__ x, const float* __restrict__ w,
                          const float* __restrict__ b){
    int plane = blockIdx.x, c = plane & 127;
    const float* xp = x + (size_t)plane*4096;
    float* op = g_xd + (size_t)plane*4096;
    float w9[9];
    #pragma unroll
    for (int i=0;i<9;i++) w9[i] = w[c*9+i];
    float bv = b[c];
    for (int idx = threadIdx.x; idx < 4096; idx += 256){
        int hh = idx >> 6, ww = idx & 63;
        float acc = bv;
        #pragma unroll
        for (int dh=-1; dh<=1; dh++){
            int h2 = hh+dh; if ((unsigned)h2 > 63u) continue;
            #pragma unroll
            for (int dw=-1; dw<=1; dw++){
                int w2 = ww+dw; if ((unsigned)w2 > 63u) continue;
                acc = fmaf(xp[h2*64+w2], w9[(dh+1)*3+(dw+1)], acc);
            }
        }
        op[idx] = acc;
    }
}

// K2: NCHW -> pixel-major + LayerNorm over 64 channels. grid 512 = (bb,h)
__global__ void k2_ln(const float* __restrict__ g1, const float* __restrict__ b1){
    int bb = blockIdx.x >> 6, h = blockIdx.x & 63;
    int br = bb >> 2, bi = bb & 3;
    __shared__ float tile[64][65];
    __shared__ float smu[64], srs[64];
    const float* src = g_xd + (size_t)(bi*128 + br*64)*4096 + h*64;
    for (int idx=threadIdx.x; idx<4096; idx+=256){
        int c = idx >> 6, w = idx & 63;
        tile[w][c] = src[(size_t)c*4096 + w];
    }
    __syncthreads();
    if (threadIdx.x < 64){
        int w = threadIdx.x; float s=0.f, ss=0.f;
        #pragma unroll 8
        for (int c=0;c<64;c++){ float v=tile[w][c]; s+=v; ss+=v*v; }
        float mu = s*(1.f/64.f);
        smu[w]=mu; srs[w]=rsqrtf(ss*(1.f/64.f)-mu*mu+1e-5f);
    }
    __syncthreads();
    float* dst = g_xln + ((size_t)bb*4096 + h*64)*64;
    for (int idx=threadIdx.x; idx<4096; idx+=256){
        int w = idx >> 6, c = idx & 63;
        dst[idx] = (tile[w][c]-smu[w])*srs[w]*g1[c] + b1[c];
    }
}

// K3: in_proj GEMM [32768,64]x[64,256] -> g_xc | g_z. grid (1024,2), 256 thr
__global__ void k3_inproj(const float* __restrict__ ipw){
    __shared__ float Ws[64][128];
    __shared__ float Xt[64][40];
    int row0 = blockIdx.x*32, jh = blockIdx.y, tid = threadIdx.x;
    for (int idx=tid; idx<8192; idx+=256){
        int c = idx & 63, j = idx >> 6;
        Ws[c][j] = ipw[(jh*128 + j)*64 + c];
    }
    for (int idx=tid; idx<2048; idx+=256){
        int c = idx & 63, r = idx >> 6;
        Xt[c][r] = g_xln[(size_t)(row0+r)*64 + c];
    }
    __syncthreads();
    int j = tid & 127, rg = tid >> 7;
    float* dstbase = (jh==0) ? (g_xc + j) : (g_z + j);
    #pragma unroll
    for (int ch=0; ch<2; ch++){
        int r0 = rg*16 + ch*8;
        float a[8] = {0,0,0,0,0,0,0,0};
        for (int c=0;c<64;c++){
            float wv = Ws[c][j];
            float4 x1 = *(const float4*)&Xt[c][r0];
            float4 x2 = *(const float4*)&Xt[c][r0+4];
            a[0]=fmaf(x1.x,wv,a[0]); a[1]=fmaf(x1.y,wv,a[1]);
            a[2]=fmaf(x1.z,wv,a[2]); a[3]=fmaf(x1.w,wv,a[3]);
            a[4]=fmaf(x2.x,wv,a[4]); a[5]=fmaf(x2.y,wv,a[5]);
            a[6]=fmaf(x2.z,wv,a[6]); a[7]=fmaf(x2.w,wv,a[7]);
        }
        #pragma unroll
        for (int rr=0; rr<8; rr++)
            dstbase[(size_t)(row0+r0+rr)*128] = a[rr];
    }
}

// K4: depthwise 3x3 + SiLU on xc (pixel-major). grid 512 = (bb,h), 128 thr
__global__ void k4_conv(const float* __restrict__ cw, const float* __restrict__ cb){
    int bb = blockIdx.x >> 6, h = blockIdx.x & 63;
    int c = threadIdx.x;
    float w9[9];
    #pragma unroll
    for (int i=0;i<9;i++) w9[i] = cw[c*9+i];
    float bv = cb[c];
    const float* base = g_xc + (size_t)bb*4096*128 + c;
    float* out = g_xc2 + ((size_t)bb*4096 + h*64)*128 + c;
    for (int w=0; w<64; w++){
        float acc = bv;
        #pragma unroll
        for (int dh=-1;dh<=1;dh++){
            int h2=h+dh; if ((unsigned)h2>63u) continue;
            #pragma unroll
            for (int dw=-1;dw<=1;dw++){
                int w2=w+dw; if ((unsigned)w2>63u) continue;
                acc = fmaf(base[(size_t)(h2*64+w2)*128], w9[(dh+1)*3+dw+1], acc);
            }
        }
        out[(size_t)w*128] = acc/(1.f+__expf(-acc));
    }
}

// K4b: gather 4 scan orders. grid 16384, 256 thr
__global__ void k4b_gather(){
    int bbk = blockIdx.x >> 9, tb = (blockIdx.x & 511)*8;
    int bb = bbk >> 2, k = bbk & 3;
    int c = threadIdx.x & 127, tl = threadIdx.x >> 7;
    #pragma unroll
    for (int i=0;i<4;i++){
        int t = tb + i*2 + tl;
        int p = pos_map(k,t);
        g_u[((size_t)bbk*4096 + t)*128 + c] = g_xc2[((size_t)bb*4096 + p)*128 + c];
    }
}

// K5: x_proj [4096,128]x[128,36] per bbk. grid 4096 = (bbk, ttile32), 288 thr
__global__ void k5_xdbl(const float* __restrict__ xpw){
    __shared__ float Wt[128][36];
    __shared__ float Xt[128][40];
    int bbk = blockIdx.x >> 7, t0 = (blockIdx.x & 127)*32;
    int k = bbk & 3, tid = threadIdx.x;
    for (int idx=tid; idx<4608; idx+=288){
        int c = idx & 127, o = idx >> 7;
        Wt[c][o] = xpw[(k*36 + o)*128 + c];
    }
    for (int idx=tid; idx<4096; idx+=288){
        int c = idx & 127, tl = idx >> 7;
        Xt[c][tl] = g_u[((size_t)bbk*4096 + t0+tl)*128 + c];
    }
    __syncthreads();
    int o = tid % 36, tg = tid / 36;
    float a[4] = {0,0,0,0};
    for (int c=0;c<128;c++){
        float wv = Wt[c][o];
        float4 xv = *(const float4*)&Xt[c][tg*4];
        a[0]=fmaf(xv.x,wv,a[0]); a[1]=fmaf(xv.y,wv,a[1]);
        a[2]=fmaf(xv.z,wv,a[2]); a[3]=fmaf(xv.w,wv,a[3]);
    }
    float* dst = g_dbl + ((size_t)bbk*4096 + t0 + tg*4)*36 + o;
    #pragma unroll
    for (int r=0;r<4;r++) dst[r*36] = a[r];
}

// K5b: delta = softplus(dts . dt_w + dt_b). grid (32,32), 128 thr
__global__ void k5b_delta(const float* __restrict__ dtw, const float* __restrict__ dtb){
    int bbk = blockIdx.x, tc = blockIdx.y;
    int k = bbk & 3, d = threadIdx.x;
    float4 wv = *(const float4*)(dtw + (k*128+d)*4);
    float bv = dtb[k*128+d];
    const float* dbl = g_dbl + ((size_t)bbk*4096 + tc*128)*36;
    float* dst = g_del + ((size_t)bbk*4096 + tc*128)*128 + d;
    for (int tl=0; tl<128; tl++){
        float4 q = *(const float4*)(dbl + (size_t)tl*36);
        float xx = q.x*wv.x + q.y*wv.y + q.z*wv.z + q.w*wv.w + bv;
        float sp = (xx > 20.f) ? xx : log1pf(__expf(xx));
        dst[(size_t)tl*128] = sp;
    }
}

// K6: selective scan. warp=(bbk, 8 d's); lane=(dl, 4 states). grid 128, 128 thr
__global__ void k6_scan(const float* __restrict__ A_logs, const float* __restrict__ Ds){
    int gw = blockIdx.x*4 + (threadIdx.x >> 5);
    int lane = threadIdx.x & 31;
    int bbk = gw >> 4, dg = gw & 15;
    int k = bbk & 3;
    int dl = lane >> 2, sg = lane & 3;
    int d = dg*8 + dl;
    float A[4], h[4] = {0.f,0.f,0.f,0.f};
    #pragma unroll
    for (int n=0;n<4;n++) A[n] = -expf(A_logs[(k*128+d)*16 + sg*4 + n]);
    float Dsd = Ds[k*128+d];
    const float* dbl = g_dbl + (size_t)bbk*4096*36;
    const float* del = g_del + (size_t)bbk*4096*128 + d;
    const float* up  = g_u   + (size_t)bbk*4096*128 + d;
    float* yo = g_y4 + (size_t)bbk*4096*128 + d;
    float4 Bb[4], Cb[4]; float db[4], ub[4];
    #pragma unroll
    for (int j=0;j<4;j++){
        Bb[j] = *(const float4*)(dbl + j*36 + 4 + sg*4);
        Cb[j] = *(const float4*)(dbl + j*36 + 20 + sg*4);
        db[j] = del[(size_t)j*128];
        ub[j] = up[(size_t)j*128];
    }
    for (int t0=0; t0<4096; t0+=4){
        #pragma unroll
        for (int j=0;j<4;j++){
            int t = t0+j;
            float delta = db[j], uu = ub[j];
            float4 Bv = Bb[j], Cv = Cb[j];
            int tn = t + 4;
            if (tn < 4096){
                Bb[j] = *(const float4*)(dbl + (size_t)tn*36 + 4 + sg*4);
                Cb[j] = *(const float4*)(dbl + (size_t)tn*36 + 20 + sg*4);
                db[j] = del[(size_t)tn*128];
                ub[j] = up[(size_t)tn*128];
            }
            float du = delta*uu;
            float dA0 = __expf(delta*A[0]);
            float dA1 = __expf(delta*A[1]);
            float dA2 = __expf(delta*A[2]);
            float dA3 = __expf(delta*A[3]);
            h[0] = fmaf(dA0, h[0], du*Bv.x);
            h[1] = fmaf(dA1, h[1], du*Bv.y);
            h[2] = fmaf(dA2, h[2], du*Bv.z);
            h[3] = fmaf(dA3, h[3], du*Bv.w);
            float acc = h[0]*Cv.x + h[1]*Cv.y + h[2]*Cv.z + h[3]*Cv.w;
            acc += __shfl_xor_sync(0xffffffffu, acc, 1);
            acc += __shfl_xor_sync(0xffffffffu, acc, 2);
            if (sg == 0) yo[(size_t)t*128] = fmaf(Dsd, uu, acc);
        }
    }
}

// K7: combine 4 directions + LN(128) + silu(z) gate. warp/pixel. grid 4096, 256 thr
__global__ void k7_comb(const float* __restrict__ ong, const float* __restrict__ onb){
    int wid = threadIdx.x >> 5, lane = threadIdx.x & 31;
    int gp = blockIdx.x*8 + wid;
    int bb = gp >> 12, l = gp & 4095;
    float v[4] = {0.f,0.f,0.f,0.f};
    #pragma unroll
    for (int k=0;k<4;k++){
        int t = pos_map(k,l);
        const float* row = g_y4 + ((size_t)(bb*4+k)*4096 + t)*128;
        #pragma unroll
        for (int i=0;i<4;i++) v[i] += row[i*32+lane];
    }
    float s=0.f, ss=0.f;
    #pragma unroll
    for (int i=0;i<4;i++){ s += v[i]; ss += v[i]*v[i]; }
    #pragma unroll
    for (int o=16;o;o>>=1){ s += __shfl_xor_sync(0xffffffffu,s,o); ss += __shfl_xor_sync(0xffffffffu,ss,o); }
    float mu = s*(1.f/128.f);
    float rs = rsqrtf(ss*(1.f/128.f)-mu*mu+1e-5f);
    const float* zr = g_z + ((size_t)bb*4096+l)*128;
    float* gr = g_g + ((size_t)bb*4096+l)*128;
    #pragma unroll
    for (int i=0;i<4;i++){
        int dd = i*32+lane;
        float zz = zr[dd];
        float gate = zz/(1.f+__expf(-zz));
        gr[dd] = ((v[i]-mu)*rs*ong[dd]+onb[dd])*gate;
    }
}

// K8: out_proj [32768,128]x[128,64] + residual, write NCHW. grid 2048, 256 thr
__global__ void k8_outproj(const float* __restrict__ opw, const float* __restrict__ scale){
    __shared__ float Ws[128][64];
    __shared__ float Xt[128][20];
    int row0 = blockIdx.x*16, tid = threadIdx.x;
    for (int idx=tid; idx<8192; idx+=256){
        int c = idx & 127, j = idx >> 7;
        Ws[c][j] = opw[j*128 + c];
    }
    for (int idx=tid; idx<2048; idx+=256){
        int c = idx & 127, r = idx >> 7;
        Xt[c][r] = g_g[(size_t)(row0+r)*128 + c];
    }
    __syncthreads();
    int j = tid & 63, rg = tid >> 6, r0 = rg*4;
    float a[4] = {0,0,0,0};
    for (int c=0;c<128;c++){
        float wv = Ws[c][j];
        float4 xv = *(const float4*)&Xt[c][r0];
        a[0]=fmaf(xv.x,wv,a[0]); a[1]=fmaf(xv.y,wv,a[1]);
        a[2]=fmaf(xv.z,wv,a[2]); a[3]=fmaf(xv.w,wv,a[3]);
    }
    float s1 = scale[0] + 1.f;
    int row = row0 + r0;
    int bb = row >> 12, l = row & 4095;
    int plane = (bb&3)*128 + (bb>>2)*64 + j;
    float4 xd4 = *(const float4*)(g_xd + (size_t)plane*4096 + l);
    float4 o4;
    o4.x = fmaf(s1, xd4.x, a[0]); o4.y = fmaf(s1, xd4.y, a[1]);
    o4.z = fmaf(s1, xd4.z, a[2]); o4.w = fmaf(s1, xd4.w, a[3]);
    *(float4*)(g_xo + (size_t)plane*4096 + l) = o4;
}

// K9: instance norm over HW + leaky relu. grid 512 planes, 256 thr
__global__ void k9_inorm(const float* __restrict__ gamma, const float* __restrict__ beta,
                         float* __restrict__ out){
    __shared__ float buf[4096];
    __shared__ float rsum[8], rsq[8];
    int plane = blockIdx.x, cch = plane & 127;
    const float* src = g_xo + (size_t)plane*4096;
    float s=0.f, ss=0.f;
    for (int idx=threadIdx.x; idx<1024; idx+=256){
        float4 v = ((const float4*)src)[idx];
        ((float4*)buf)[idx] = v;
        s += v.x+v.y+v.z+v.w;
        ss += v.x*v.x+v.y*v.y+v.z*v.z+v.w*v.w;
    }
    #pragma unroll
    for (int o=16;o;o>>=1){ s += __shfl_xor_sync(0xffffffffu,s,o); ss += __shfl_xor_sync(0xffffffffu,ss,o); }
    int wid = threadIdx.x >> 5;
    if ((threadIdx.x & 31) == 0){ rsum[wid]=s; rsq[wid]=ss; }
    __syncthreads();
    if (threadIdx.x == 0){
        float ts=0.f, tss=0.f;
        #pragma unroll
        for (int i=0;i<8;i++){ ts += rsum[i]; tss += rsq[i]; }
        float mu = ts*(1.f/4096.f);
        rsum[0] = mu;
        rsq[0]  = rsqrtf(tss*(1.f/4096.f)-mu*mu+1e-5f);
    }
    __syncthreads();
    float mu = rsum[0], rr = rsq[0];
    float gm = gamma[cch], bt = beta[cch];
    float* dst = out + (size_t)plane*4096;
    for (int idx=threadIdx.x; idx<4096; idx+=256){
        float v = (buf[idx]-mu)*rr*gm + bt;
        dst[idx] = v > 0.f ? v : 0.01f*v;
    }
}

extern "C" void kernel_launch(void* const* d_in, const int* in_sizes, int n_in,
                              void* d_out, int out_size) {
    const float* x        = (const float*)d_in[0];
    const float* dw_w     = (const float*)d_in[1];
    const float* dw_b     = (const float*)d_in[2];
    const float* scale    = (const float*)d_in[3];
    const float* ln1_g    = (const float*)d_in[4];
    const float* ln1_b    = (const float*)d_in[5];
    const float* in_proj  = (const float*)d_in[6];
    const float* conv_w   = (const float*)d_in[7];
    const float* conv_b   = (const float*)d_in[8];
    const float* x_proj   = (const float*)d_in[9];
    const float* dt_w     = (const float*)d_in[10];
    const float* dt_b     = (const float*)d_in[11];
    const float* A_logs   = (const float*)d_in[12];
    const float* Ds       = (const float*)d_in[13];
    const float* on_g     = (const float*)d_in[14];
    const float* on_b     = (const float*)d_in[15];
    const float* out_proj = (const float*)d_in[16];
    const float* in_gamma = (const float*)d_in[17];
    const float* in_beta  = (const float*)d_in[18];
    float* out = (float*)d_out;

    k1_dwconv  <<<512, 256>>>(x, dw_w, dw_b);
    k2_ln      <<<512, 256>>>(ln1_g, ln1_b);
    k3_inproj  <<<dim3(1024,2), 256>>>(in_proj);
    k4_conv    <<<512, 128>>>(conv_w, conv_b);
    k4b_gather <<<16384, 256>>>();
    k5_xdbl    <<<4096, 288>>>(x_proj);
    k5b_delta  <<<dim3(32,32), 128>>>(dt_w, dt_b);
    k6_scan    <<<128, 128>>>(A_logs, Ds);
    k7_comb    <<<4096, 256>>>(on_g, on_b);
    k8_outproj <<<2048, 256>>>(out_proj, scale);
    k9_inorm   <<<512, 256>>>(in_gamma, in_beta, out);
}

// round 4
// speedup vs baseline: 2.9428x; 2.9428x over previous
#include <cuda_runtime.h>
#include <cuda_bf16.h>

// B=4,C=128,H=W=64,L=4096, D=64, DI=128, N=16, R=4, K=4. bb=branch*4+b (8), bbk=bb*4+k (32)

__device__ float g_xd  [4*128*4096];     // dwconv(x) NCHW
__device__ float g_xln [8*4096*64];      // LN output pixel-major
__device__ float g_xc  [8*4096*128];     // in_proj xc half
__device__ float g_z   [8*4096*128];     // in_proj z half
__device__ float g_xc2 [8*4096*128];     // conv+silu, pixel-major
__device__ float g_u2  [8*4096*128];     // transpose-order copy of xc2 (for k=1,3)
__device__ float g_dts [32*4096*4];      // x_proj dts part
__device__ float g_bc  [32*4096*32];     // x_proj B(16)|C(16) part
__device__ float g_del [32*4096*128];    // softplus delta
__device__ float g_hc  [32*16*128*16];   // pass1 chunk-final local state
__device__ float g_cp  [32*16*128*16];   // pass1 chunk cumprod(a)
__device__ float g_hi  [32*16*128*16];   // pass2 chunk incoming state
__device__ float g_y4  [32*4096*128];    // scan outputs (C·h only)
__device__ float g_g   [8*4096*128];     // gated LN(y)
__device__ float g_xo  [4*128*4096];     // pre-instance-norm NCHW
__device__ float g_A   [8192];           // -exp(A_logs)
__device__ float g_dsum[128];            // sum_k Ds[k][d]

__device__ __forceinline__ int pos_map(int k, int t){
    int tt = (k >= 2) ? (4095 - t) : t;
    if (k & 1) tt = ((tt & 63) << 6) | (tt >> 6);
    return tt;
}

// u row base (element 0) + stride (in floats) for scan order k of batch bb
__device__ __forceinline__ const float* u_base(int bb, int k, int t0, int& us){
    const float* arr = (k & 1) ? g_u2 : g_xc2;
    int p0 = (k >= 2) ? (4095 - t0) : t0;
    us = (k >= 2) ? -128 : 128;
    return arr + ((size_t)bb*4096 + p0)*128;
}

// K0: tiny precompute
__global__ void k0_prep(const float* __restrict__ A_logs, const float* __restrict__ Ds){
    int i = blockIdx.x*256 + threadIdx.x;
    if (i < 8192) g_A[i] = -expf(A_logs[i]);
    if (i < 128)  g_dsum[i] = Ds[i] + Ds[128+i] + Ds[256+i] + Ds[384+i];
}

// K1: depthwise 3x3 on x (NCHW), smem-tiled. grid 2048 = (plane, strip16), 256 thr
__global__ void k1_dwconv(const float* __restrict__ x, const float* __restrict__ w,
                          const float* __restrict__ b){
    int plane = blockIdx.x >> 2, strip = blockIdx.x & 3;
    int c = plane & 127, h0 = strip*16;
    __shared__ float t[18][64];
    const float* xp = x + (size_t)plane*4096;
    for (int i=threadIdx.x; i<1152; i+=256){
        int r = i >> 6, ww = i & 63, hh = h0-1+r;
        t[r][ww] = ((unsigned)hh < 64u) ? xp[hh*64+ww] : 0.f;
    }
    __syncthreads();
    float w9[9];
    #pragma unroll
    for (int i=0;i<9;i++) w9[i] = w[c*9+i];
    float bv = b[c];
    float* op = g_xd + (size_t)plane*4096 + h0*64;
    for (int i=threadIdx.x; i<1024; i+=256){
        int r = i >> 6, ww = i & 63;
        float acc = bv;
        #pragma unroll
        for (int dh=0; dh<3; dh++){
            #pragma unroll
            for (int dw=-1; dw<=1; dw++){
                int w2 = ww+dw;
                if ((unsigned)w2 < 64u) acc = fmaf(t[r+dh][w2], w9[dh*3+dw+1], acc);
            }
        }
        op[i] = acc;
    }
}

// K2: NCHW -> pixel-major + LayerNorm(64). grid 512 = (bb,h), 256 thr
__global__ void k2_ln(const float* __restrict__ g1, const float* __restrict__ b1){
    int bb = blockIdx.x >> 6, h = blockIdx.x & 63;
    int br = bb >> 2, bi = bb & 3;
    __shared__ float tile[64][65];
    __shared__ float smu[64], srs[64];
    const float* src = g_xd + (size_t)(bi*128 + br*64)*4096 + h*64;
    for (int idx=threadIdx.x; idx<4096; idx+=256){
        int c = idx >> 6, w = idx & 63;
        tile[w][c] = src[(size_t)c*4096 + w];
    }
    __syncthreads();
    if (threadIdx.x < 64){
        int w = threadIdx.x; float s=0.f, ss=0.f;
        #pragma unroll 8
        for (int c=0;c<64;c++){ float v=tile[w][c]; s+=v; ss+=v*v; }
        float mu = s*(1.f/64.f);
        smu[w]=mu; srs[w]=rsqrtf(ss*(1.f/64.f)-mu*mu+1e-5f);
    }
    __syncthreads();
    float* dst = g_xln + ((size_t)bb*4096 + h*64)*64;
    for (int idx=threadIdx.x; idx<4096; idx+=256){
        int w = idx >> 6, c = idx & 63;
        dst[idx] = (tile[w][c]-smu[w])*srs[w]*g1[c] + b1[c];
    }
}

// K3: in_proj GEMM [32768,64]x[64,256]. grid (1024,2), 256 thr
__global__ void k3_inproj(const float* __restrict__ ipw){
    __shared__ float Ws[64][128];
    __shared__ float Xt[64][40];
    int row0 = blockIdx.x*32, jh = blockIdx.y, tid = threadIdx.x;
    for (int idx=tid; idx<8192; idx+=256){
        int c = idx & 63, j = idx >> 6;
        Ws[c][j] = ipw[(jh*128 + j)*64 + c];
    }
    for (int idx=tid; idx<2048; idx+=256){
        int c = idx & 63, r = idx >> 6;
        Xt[c][r] = g_xln[(size_t)(row0+r)*64 + c];
    }
    __syncthreads();
    int j = tid & 127, rg = tid >> 7;
    float* dstbase = (jh==0) ? (g_xc + j) : (g_z + j);
    #pragma unroll
    for (int ch=0; ch<2; ch++){
        int r0 = rg*16 + ch*8;
        float a[8] = {0,0,0,0,0,0,0,0};
        for (int c=0;c<64;c++){
            float wv = Ws[c][j];
            float4 x1 = *(const float4*)&Xt[c][r0];
            float4 x2 = *(const float4*)&Xt[c][r0+4];
            a[0]=fmaf(x1.x,wv,a[0]); a[1]=fmaf(x1.y,wv,a[1]);
            a[2]=fmaf(x1.z,wv,a[2]); a[3]=fmaf(x1.w,wv,a[3]);
            a[4]=fmaf(x2.x,wv,a[4]); a[5]=fmaf(x2.y,wv,a[5]);
            a[6]=fmaf(x2.z,wv,a[6]); a[7]=fmaf(x2.w,wv,a[7]);
        }
        #pragma unroll
        for (int rr=0; rr<8; rr++)
            dstbase[(size_t)(row0+r0+rr)*128] = a[rr];
    }
}

// K4: depthwise 3x3 + SiLU on xc (pixel-major), smem-tiled by c-group.
// grid 1024 = (bb8, strip16, cg8), 256 thr
__global__ void k4_conv(const float* __restrict__ cw, const float* __restrict__ cb){
    int bb = blockIdx.x >> 7;
    int strip = (blockIdx.x >> 3) & 15;
    int cg = blockIdx.x & 7;
    int h0 = strip*4, c0 = cg*16;
    __shared__ float t[6][64][16];
    const float* src = g_xc + (size_t)bb*4096*128 + c0;
    for (int i=threadIdx.x; i<6144; i+=256){
        int cl = i & 15, ww = (i>>4) & 63, r = i >> 10;
        int hh = h0-1+r;
        t[r][ww][cl] = ((unsigned)hh < 64u) ? src[(size_t)(hh*64+ww)*128 + cl] : 0.f;
    }
    __syncthreads();
    int cl = threadIdx.x & 15, c = c0 + cl;
    float w9[9];
    #pragma unroll
    for (int i=0;i<9;i++) w9[i] = cw[c*9+i];
    float bv = cb[c];
    float* dst = g_xc2 + (size_t)bb*4096*128 + c0 + cl;
    for (int i=threadIdx.x; i<4096; i+=256){
        int ww = (i>>4) & 63, r = i >> 10;
        float acc = bv;
        #pragma unroll
        for (int dh=0; dh<3; dh++){
            #pragma unroll
            for (int dw=-1; dw<=1; dw++){
                int w2 = ww+dw;
                if ((unsigned)w2 < 64u) acc = fmaf(t[r+dh][w2][cl], w9[dh*3+dw+1], acc);
            }
        }
        acc = acc/(1.f+__expf(-acc));
        dst[(size_t)((h0+r)*64+ww)*128] = acc;
    }
}

// K4b: materialize transpose order only. grid (8,128), 256 thr
__global__ void k4b_gather(){
    int bb = blockIdx.x, tb = blockIdx.y*32;
    int c = threadIdx.x & 127, tl = threadIdx.x >> 7;
    #pragma unroll
    for (int i=0;i<16;i++){
        int t = tb + i*2 + tl;
        int p = ((t & 63) << 6) | (t >> 6);
        g_u2[((size_t)bb*4096 + t)*128 + c] = g_xc2[((size_t)bb*4096 + p)*128 + c];
    }
}

// K5: x_proj [4096,128]x[128,36] per bbk -> g_dts | g_bc. grid 4096, 288 thr
__global__ void k5_xdbl(const float* __restrict__ xpw){
    __shared__ float Wt[128][36];
    __shared__ float Xt[128][40];
    int bbk = blockIdx.x >> 7, t0 = (blockIdx.x & 127)*32;
    int bb = bbk >> 2, k = bbk & 3, tid = threadIdx.x;
    int us; const float* ub = u_base(bb, k, t0, us);
    for (int idx=tid; idx<4608; idx+=288){
        int c = idx & 127, o = idx >> 7;
        Wt[c][o] = xpw[(k*36 + o)*128 + c];
    }
    for (int idx=tid; idx<4096; idx+=288){
        int c = idx & 127, tl = idx >> 7;
        Xt[c][tl] = ub[(long)tl*us + c];
    }
    __syncthreads();
    int o = tid % 36, tg = tid / 36;
    float a[4] = {0,0,0,0};
    for (int c=0;c<128;c++){
        float wv = Wt[c][o];
        float4 xv = *(const float4*)&Xt[c][tg*4];
        a[0]=fmaf(xv.x,wv,a[0]); a[1]=fmaf(xv.y,wv,a[1]);
        a[2]=fmaf(xv.z,wv,a[2]); a[3]=fmaf(xv.w,wv,a[3]);
    }
    if (o < 4){
        #pragma unroll
        for (int r=0;r<4;r++)
            g_dts[((size_t)bbk*4096 + t0 + tg*4 + r)*4 + o] = a[r];
    } else {
        #pragma unroll
        for (int r=0;r<4;r++)
            g_bc[((size_t)bbk*4096 + t0 + tg*4 + r)*32 + (o-4)] = a[r];
    }
}

// K5b: delta = softplus(dts . dt_w + dt_b). grid (32,64), 256 thr
__global__ void k5b_delta(const float* __restrict__ dtw, const float* __restrict__ dtb){
    __shared__ float sdts[64][4];
    int bbk = blockIdx.x, k = bbk & 3;
    int t0 = blockIdx.y*64;
    int d = threadIdx.x & 127, sub = threadIdx.x >> 7;
    if (threadIdx.x < 256){
        int i = threadIdx.x;
        if (i < 256) ((float*)sdts)[i] = g_dts[((size_t)bbk*4096 + t0)*4 + i];
    }
    __syncthreads();
    float4 wv = *(const float4*)(dtw + (k*128+d)*4);
    float bv = dtb[k*128+d];
    float* dst = g_del + ((size_t)bbk*4096 + t0 + sub*32)*128 + d;
    #pragma unroll 4
    for (int tl=0; tl<32; tl++){
        float4 q = *(const float4*)sdts[sub*32 + tl];
        float xx = q.x*wv.x + q.y*wv.y + q.z*wv.z + q.w*wv.w + bv;
        float sp = (xx > 20.f) ? xx : log1pf(__expf(xx));
        dst[(size_t)tl*128] = sp;
    }
}

// K6a: pass1 chunk-local scan: store final h + cumprod(a).
// warp = (bbk32, dg16, chunk16) -> 8192 warps. grid 1024, 256 thr
__global__ void k6a_scan1(){
    int gw = blockIdx.x*8 + (threadIdx.x >> 5);
    int lane = threadIdx.x & 31;
    int chunk = gw & 15, dg = (gw >> 4) & 15, bbk = gw >> 8;
    int bb = bbk >> 2, k = bbk & 3;
    int dl = lane >> 2, sg = lane & 3, d = dg*8 + dl;
    float4 Av = *(const float4*)(g_A + (size_t)(k*128+d)*16 + sg*4);
    float h0=0,h1=0,h2=0,h3=0, c0=1,c1=1,c2=1,c3=1;
    int t0 = chunk*256;
    const float* del = g_del + ((size_t)bbk*4096 + t0)*128 + d;
    const float* bc  = g_bc  + ((size_t)bbk*4096 + t0)*32 + sg*4;
    int us; const float* ub = u_base(bb, k, t0, us) + d;
    #pragma unroll 4
    for (int t=0; t<256; t++){
        float delta = del[(size_t)t*128];
        float uu = ub[(long)t*us];
        float4 B = *(const float4*)(bc + (size_t)t*32);
        float du = delta*uu;
        float a0 = __expf(delta*Av.x), a1 = __expf(delta*Av.y);
        float a2 = __expf(delta*Av.z), a3 = __expf(delta*Av.w);
        h0 = fmaf(a0,h0,du*B.x); h1 = fmaf(a1,h1,du*B.y);
        h2 = fmaf(a2,h2,du*B.z); h3 = fmaf(a3,h3,du*B.w);
        c0*=a0; c1*=a1; c2*=a2; c3*=a3;
    }
    size_t so = ((size_t)(bbk*16+chunk)*128 + d)*16 + sg*4;
    float4 st; st.x=h0; st.y=h1; st.z=h2; st.w=h3;
    *(float4*)(g_hc + so) = st;
    st.x=c0; st.y=c1; st.z=c2; st.w=c3;
    *(float4*)(g_cp + so) = st;
}

// K6b: sequential scan over 16 chunk summaries. grid 256, 256 thr
__global__ void k6b_scan2(){
    int idx = blockIdx.x*256 + threadIdx.x;     // 65536 = bbk*2048 + d*16 + n
    int bbk = idx >> 11, rem = idx & 2047;
    float H = 0.f;
    #pragma unroll
    for (int c=0; c<16; c++){
        size_t o = ((size_t)(bbk*16+c))*2048 + rem;
        g_hi[o] = H;
        H = g_cp[o]*H + g_hc[o];
    }
}

// K6c: pass3 full scan with correct incoming state, emit y = C.h
__global__ void k6c_scan3(){
    int gw = blockIdx.x*8 + (threadIdx.x >> 5);
    int lane = threadIdx.x & 31;
    int chunk = gw & 15, dg = (gw >> 4) & 15, bbk = gw >> 8;
    int bb = bbk >> 2, k = bbk & 3;
    int dl = lane >> 2, sg = lane & 3, d = dg*8 + dl;
    float4 Av = *(const float4*)(g_A + (size_t)(k*128+d)*16 + sg*4);
    size_t so = ((size_t)(bbk*16+chunk)*128 + d)*16 + sg*4;
    float4 hi = *(const float4*)(g_hi + so);
    float h0=hi.x, h1=hi.y, h2=hi.z, h3=hi.w;
    int t0 = chunk*256;
    const float* del = g_del + ((size_t)bbk*4096 + t0)*128 + d;
    const float* bc  = g_bc  + ((size_t)bbk*4096 + t0)*32;
    int us; const float* ub = u_base(bb, k, t0, us) + d;
    float* yo = g_y4 + ((size_t)bbk*4096 + t0)*128 + d;
    #pragma unroll 4
    for (int t=0; t<256; t++){
        float delta = del[(size_t)t*128];
        float uu = ub[(long)t*us];
        float4 B = *(const float4*)(bc + (size_t)t*32 + sg*4);
        float4 C = *(const float4*)(bc + (size_t)t*32 + 16 + sg*4);
        float du = delta*uu;
        float a0 = __expf(delta*Av.x), a1 = __expf(delta*Av.y);
        float a2 = __expf(delta*Av.z), a3 = __expf(delta*Av.w);
        h0 = fmaf(a0,h0,du*B.x); h1 = fmaf(a1,h1,du*B.y);
        h2 = fmaf(a2,h2,du*B.z); h3 = fmaf(a3,h3,du*B.w);
        float acc = h0*C.x + h1*C.y + h2*C.z + h3*C.w;
        acc += __shfl_xor_sync(0xffffffffu, acc, 1);
        acc += __shfl_xor_sync(0xffffffffu, acc, 2);
        if (sg == 0) yo[(size_t)t*128] = acc;
    }
}

// K7: combine 4 dirs + Dsum*u + LN(128) + silu(z) gate. warp/pixel. grid 4096, 256 thr
__global__ void k7_comb(const float* __restrict__ ong, const float* __restrict__ onb){
    int wid = threadIdx.x >> 5, lane = threadIdx.x & 31;
    int gp = blockIdx.x*8 + wid;
    int bb = gp >> 12, l = gp & 4095;
    const float* xr = g_xc2 + ((size_t)bb*4096 + l)*128;
    float v[4];
    #pragma unroll
    for (int i=0;i<4;i++){
        int dd = i*32 + lane;
        v[i] = g_dsum[dd]*xr[dd];
    }
    #pragma unroll
    for (int k=0;k<4;k++){
        int t = pos_map(k,l);
        const float* row = g_y4 + ((size_t)(bb*4+k)*4096 + t)*128;
        #pragma unroll
        for (int i=0;i<4;i++) v[i] += row[i*32+lane];
    }
    float s=0.f, ss=0.f;
    #pragma unroll
    for (int i=0;i<4;i++){ s += v[i]; ss += v[i]*v[i]; }
    #pragma unroll
    for (int o=16;o;o>>=1){ s += __shfl_xor_sync(0xffffffffu,s,o); ss += __shfl_xor_sync(0xffffffffu,ss,o); }
    float mu = s*(1.f/128.f);
    float rs = rsqrtf(ss*(1.f/128.f)-mu*mu+1e-5f);
    const float* zr = g_z + ((size_t)bb*4096+l)*128;
    float* gr = g_g + ((size_t)bb*4096+l)*128;
    #pragma unroll
    for (int i=0;i<4;i++){
        int dd = i*32+lane;
        float zz = zr[dd];
        float gate = zz/(1.f+__expf(-zz));
        gr[dd] = ((v[i]-mu)*rs*ong[dd]+onb[dd])*gate;
    }
}

// K8: out_proj [32768,128]x[128,64] + residual, write NCHW. grid 2048, 256 thr
__global__ void k8_outproj(const float* __restrict__ opw, const float* __restrict__ scale){
    __shared__ float Ws[128][64];
    __shared__ float Xt[128][20];
    int row0 = blockIdx.x*16, tid = threadIdx.x;
    for (int idx=tid; idx<8192; idx+=256){
        int c = idx & 127, j = idx >> 7;
        Ws[c][j] = opw[j*128 + c];
    }
    for (int idx=tid; idx<2048; idx+=256){
        int c = idx & 127, r = idx >> 7;
        Xt[c][r] = g_g[(size_t)(row0+r)*128 + c];
    }
    __syncthreads();
    int j = tid & 63, rg = tid >> 6, r0 = rg*4;
    float a[4] = {0,0,0,0};
    for (int c=0;c<128;c++){
        float wv = Ws[c][j];
        float4 xv = *(const float4*)&Xt[c][r0];
        a[0]=fmaf(xv.x,wv,a[0]); a[1]=fmaf(xv.y,wv,a[1]);
        a[2]=fmaf(xv.z,wv,a[2]); a[3]=fmaf(xv.w,wv,a[3]);
    }
    float s1 = scale[0] + 1.f;
    int row = row0 + r0;
    int bb = row >> 12, l = row & 4095;
    int plane = (bb&3)*128 + (bb>>2)*64 + j;
    float4 xd4 = *(const float4*)(g_xd + (size_t)plane*4096 + l);
    float4 o4;
    o4.x = fmaf(s1, xd4.x, a[0]); o4.y = fmaf(s1, xd4.y, a[1]);
    o4.z = fmaf(s1, xd4.z, a[2]); o4.w = fmaf(s1, xd4.w, a[3]);
    *(float4*)(g_xo + (size_t)plane*4096 + l) = o4;
}

// K9: instance norm over HW + leaky relu. grid 512 planes, 256 thr
__global__ void k9_inorm(const float* __restrict__ gamma, const float* __restrict__ beta,
                         float* __restrict__ out){
    __shared__ float buf[4096];
    __shared__ float rsum[8], rsq[8];
    int plane = blockIdx.x, cch = plane & 127;
    const float* src = g_xo + (size_t)plane*4096;
    float s=0.f, ss=0.f;
    for (int idx=threadIdx.x; idx<1024; idx+=256){
        float4 v = ((const float4*)src)[idx];
        ((float4*)buf)[idx] = v;
        s += v.x+v.y+v.z+v.w;
        ss += v.x*v.x+v.y*v.y+v.z*v.z+v.w*v.w;
    }
    #pragma unroll
    for (int o=16;o;o>>=1){ s += __shfl_xor_sync(0xffffffffu,s,o); ss += __shfl_xor_sync(0xffffffffu,ss,o); }
    int wid = threadIdx.x >> 5;
    if ((threadIdx.x & 31) == 0){ rsum[wid]=s; rsq[wid]=ss; }
    __syncthreads();
    if (threadIdx.x == 0){
        float ts=0.f, tss=0.f;
        #pragma unroll
        for (int i=0;i<8;i++){ ts += rsum[i]; tss += rsq[i]; }
        float mu = ts*(1.f/4096.f);
        rsum[0] = mu;
        rsq[0]  = rsqrtf(tss*(1.f/4096.f)-mu*mu+1e-5f);
    }
    __syncthreads();
    float mu = rsum[0], rr = rsq[0];
    float gm = gamma[cch], bt = beta[cch];
    float* dst = out + (size_t)plane*4096;
    for (int idx=threadIdx.x; idx<4096; idx+=256){
        float v = (buf[idx]-mu)*rr*gm + bt;
        dst[idx] = v > 0.f ? v : 0.01f*v;
    }
}

extern "C" void kernel_launch(void* const* d_in, const int* in_sizes, int n_in,
                              void* d_out, int out_size) {
    const float* x        = (const float*)d_in[0];
    const float* dw_w     = (const float*)d_in[1];
    const float* dw_b     = (const float*)d_in[2];
    const float* scale    = (const float*)d_in[3];
    const float* ln1_g    = (const float*)d_in[4];
    const float* ln1_b    = (const float*)d_in[5];
    const float* in_proj  = (const float*)d_in[6];
    const float* conv_w   = (const float*)d_in[7];
    const float* conv_b   = (const float*)d_in[8];
    const float* x_proj   = (const float*)d_in[9];
    const float* dt_w     = (const float*)d_in[10];
    const float* dt_b     = (const float*)d_in[11];
    const float* A_logs   = (const float*)d_in[12];
    const float* Ds       = (const float*)d_in[13];
    const float* on_g     = (const float*)d_in[14];
    const float* on_b     = (const float*)d_in[15];
    const float* out_proj = (const float*)d_in[16];
    const float* in_gamma = (const float*)d_in[17];
    const float* in_beta  = (const float*)d_in[18];
    float* out = (float*)d_out;

    k0_prep    <<<32, 256>>>(A_logs, Ds);
    k1_dwconv  <<<2048, 256>>>(x, dw_w, dw_b);
    k2_ln      <<<512, 256>>>(ln1_g, ln1_b);
    k3_inproj  <<<dim3(1024,2), 256>>>(in_proj);
    k4_conv    <<<1024, 256>>>(conv_w, conv_b);
    k4b_gather <<<dim3(8,128), 256>>>();
    k5_xdbl    <<<4096, 288>>>(x_proj);
    k5b_delta  <<<dim3(32,64), 256>>>(dt_w, dt_b);
    k6a_scan1  <<<1024, 256>>>();
    k6b_scan2  <<<256, 256>>>();
    k6c_scan3  <<<1024, 256>>>();
    k7_comb    <<<4096, 256>>>(on_g, on_b);
    k8_outproj <<<2048, 256>>>(out_proj, scale);
    k9_inorm   <<<512, 256>>>(in_gamma, in_beta, out);
}

// round 5
// speedup vs baseline: 4.2359x; 1.4394x over previous
#include <cuda_runtime.h>
#include <cuda_bf16.h>

// B=4,C=128,H=W=64,L=4096, D=64, DI=128, N=16, R=4, K=4. bb=branch*4+b (8), bbk=bb*4+k (32)
// scan: 32 chunks x 128 steps

__device__ float g_xd  [4*128*4096];
__device__ float g_xln [8*4096*64];
__device__ float g_xc  [8*4096*128];
__device__ float g_z   [8*4096*128];
__device__ float g_xc2 [8*4096*128];
__device__ float g_u2  [8*4096*128];
__device__ float g_dts [32*4096*4];
__device__ float g_bc  [32*4096*32];
__device__ float g_del [32*4096*128];
__device__ float g_hc  [32*32*128*16];
__device__ float g_cp  [32*32*128*16];
__device__ float g_hi  [32*32*128*16];
__device__ float g_y4  [32*4096*128];
__device__ float g_g   [8*4096*128];
__device__ float g_xo  [4*128*4096];
__device__ float g_A   [8192];
__device__ float g_dsum[128];

__device__ __forceinline__ int pos_map(int k, int t){
    int tt = (k >= 2) ? (4095 - t) : t;
    if (k & 1) tt = ((tt & 63) << 6) | (tt >> 6);
    return tt;
}

__device__ __forceinline__ const float* u_base(int bb, int k, int t0, int& us){
    const float* arr = (k & 1) ? g_u2 : g_xc2;
    int p0 = (k >= 2) ? (4095 - t0) : t0;
    us = (k >= 2) ? -128 : 128;
    return arr + ((size_t)bb*4096 + p0)*128;
}

__global__ void k0_prep(const float* __restrict__ A_logs, const float* __restrict__ Ds){
    int i = blockIdx.x*256 + threadIdx.x;
    if (i < 8192) g_A[i] = -expf(A_logs[i]);
    if (i < 128)  g_dsum[i] = Ds[i] + Ds[128+i] + Ds[256+i] + Ds[384+i];
}

// K1: depthwise 3x3 on x (NCHW), smem-tiled. grid 2048 = (plane, strip4), 256 thr
__global__ void k1_dwconv(const float* __restrict__ x, const float* __restrict__ w,
                          const float* __restrict__ b){
    int plane = blockIdx.x >> 2, strip = blockIdx.x & 3;
    int c = plane & 127, h0 = strip*16;
    __shared__ float t[18][64];
    const float* xp = x + (size_t)plane*4096;
    for (int i=threadIdx.x; i<1152; i+=256){
        int r = i >> 6, ww = i & 63, hh = h0-1+r;
        t[r][ww] = ((unsigned)hh < 64u) ? xp[hh*64+ww] : 0.f;
    }
    __syncthreads();
    float w9[9];
    #pragma unroll
    for (int i=0;i<9;i++) w9[i] = w[c*9+i];
    float bv = b[c];
    float* op = g_xd + (size_t)plane*4096 + h0*64;
    for (int i=threadIdx.x; i<1024; i+=256){
        int r = i >> 6, ww = i & 63;
        float acc = bv;
        #pragma unroll
        for (int dh=0; dh<3; dh++){
            #pragma unroll
            for (int dw=-1; dw<=1; dw++){
                int w2 = ww+dw;
                if ((unsigned)w2 < 64u) acc = fmaf(t[r+dh][w2], w9[dh*3+dw+1], acc);
            }
        }
        op[i] = acc;
    }
}

// K2: NCHW -> pixel-major + LayerNorm(64). grid 512 = (bb,h), 256 thr
__global__ void k2_ln(const float* __restrict__ g1, const float* __restrict__ b1){
    int bb = blockIdx.x >> 6, h = blockIdx.x & 63;
    int br = bb >> 2, bi = bb & 3;
    __shared__ float tile[64][65];
    __shared__ float smu[64], srs[64];
    const float* src = g_xd + (size_t)(bi*128 + br*64)*4096 + h*64;
    for (int idx=threadIdx.x; idx<4096; idx+=256){
        int c = idx >> 6, w = idx & 63;
        tile[w][c] = src[(size_t)c*4096 + w];
    }
    __syncthreads();
    if (threadIdx.x < 64){
        int w = threadIdx.x; float s=0.f, ss=0.f;
        #pragma unroll 8
        for (int c=0;c<64;c++){ float v=tile[w][c]; s+=v; ss+=v*v; }
        float mu = s*(1.f/64.f);
        smu[w]=mu; srs[w]=rsqrtf(ss*(1.f/64.f)-mu*mu+1e-5f);
    }
    __syncthreads();
    float* dst = g_xln + ((size_t)bb*4096 + h*64)*64;
    for (int idx=threadIdx.x; idx<4096; idx+=256){
        int w = idx >> 6, c = idx & 63;
        dst[idx] = (tile[w][c]-smu[w])*srs[w]*g1[c] + b1[c];
    }
}

// K3: in_proj GEMM [32768,64]x[64,256], 128x128 tile, 8x8/thread, K-chunk 32.
// grid (256,2), 256 thr
__global__ void k3_inproj(const float* __restrict__ ipw){
    __shared__ float As[32][132];
    __shared__ float Ws[32][132];
    int row0 = blockIdx.x*128, jh = blockIdx.y, tid = threadIdx.x;
    int ct = tid & 15, rt = tid >> 4;
    float acc[8][8];
    #pragma unroll
    for (int i=0;i<8;i++)
        #pragma unroll
        for (int j=0;j<8;j++) acc[i][j]=0.f;
    #pragma unroll
    for (int kc=0; kc<2; kc++){
        for (int idx=tid; idx<4096; idx+=256){
            int r = idx >> 5, c = idx & 31;
            As[c][r] = g_xln[(size_t)(row0+r)*64 + kc*32 + c];
        }
        for (int idx=tid; idx<4096; idx+=256){
            int j = idx >> 5, c = idx & 31;
            Ws[c][j] = ipw[(jh*128+j)*64 + kc*32 + c];
        }
        __syncthreads();
        #pragma unroll 4
        for (int c=0;c<32;c++){
            float4 a0 = *(const float4*)&As[c][rt*4];
            float4 a1 = *(const float4*)&As[c][rt*4+64];
            float4 w0 = *(const float4*)&Ws[c][ct*4];
            float4 w1 = *(const float4*)&Ws[c][ct*4+64];
            float ar[8] = {a0.x,a0.y,a0.z,a0.w,a1.x,a1.y,a1.z,a1.w};
            float wr[8] = {w0.x,w0.y,w0.z,w0.w,w1.x,w1.y,w1.z,w1.w};
            #pragma unroll
            for (int i=0;i<8;i++)
                #pragma unroll
                for (int j=0;j<8;j++) acc[i][j] = fmaf(ar[i], wr[j], acc[i][j]);
        }
        __syncthreads();
    }
    float* dstbase = (jh==0) ? g_xc : g_z;
    #pragma unroll
    for (int ri=0;ri<8;ri++){
        int r = row0 + rt*4 + (ri&3) + (ri>>2)*64;
        #pragma unroll
        for (int jj=0;jj<2;jj++){
            float4 v = make_float4(acc[ri][jj*4],acc[ri][jj*4+1],acc[ri][jj*4+2],acc[ri][jj*4+3]);
            *(float4*)&dstbase[(size_t)r*128 + ct*4 + jj*64] = v;
        }
    }
}

// K4: depthwise 3x3 + SiLU on xc (pixel-major), smem-tiled by c-group.
// grid 1024 = (bb8, strip16, cg8), 256 thr
__global__ void k4_conv(const float* __restrict__ cw, const float* __restrict__ cb){
    int bb = blockIdx.x >> 7;
    int strip = (blockIdx.x >> 3) & 15;
    int cg = blockIdx.x & 7;
    int h0 = strip*4, c0 = cg*16;
    __shared__ float t[6][64][16];
    const float* src = g_xc + (size_t)bb*4096*128 + c0;
    for (int i=threadIdx.x; i<6144; i+=256){
        int cl = i & 15, ww = (i>>4) & 63, r = i >> 10;
        int hh = h0-1+r;
        t[r][ww][cl] = ((unsigned)hh < 64u) ? src[(size_t)(hh*64+ww)*128 + cl] : 0.f;
    }
    __syncthreads();
    int cl = threadIdx.x & 15, c = c0 + cl;
    float w9[9];
    #pragma unroll
    for (int i=0;i<9;i++) w9[i] = cw[c*9+i];
    float bv = cb[c];
    float* dst = g_xc2 + (size_t)bb*4096*128 + c0 + cl;
    for (int i=threadIdx.x; i<4096; i+=256){
        int ww = (i>>4) & 63, r = i >> 10;
        float acc = bv;
        #pragma unroll
        for (int dh=0; dh<3; dh++){
            #pragma unroll
            for (int dw=-1; dw<=1; dw++){
                int w2 = ww+dw;
                if ((unsigned)w2 < 64u) acc = fmaf(t[r+dh][w2][cl], w9[dh*3+dw+1], acc);
            }
        }
        acc = acc/(1.f+__expf(-acc));
        dst[(size_t)((h0+r)*64+ww)*128] = acc;
    }
}

// K4b: materialize transpose order. grid (8,128), 256 thr
__global__ void k4b_gather(){
    int bb = blockIdx.x, tb = blockIdx.y*32;
    int c = threadIdx.x & 127, tl = threadIdx.x >> 7;
    #pragma unroll
    for (int i=0;i<16;i++){
        int t = tb + i*2 + tl;
        int p = ((t & 63) << 6) | (t >> 6);
        g_u2[((size_t)bb*4096 + t)*128 + c] = g_xc2[((size_t)bb*4096 + p)*128 + c];
    }
}

// K5: x_proj [4096,128]x[128,36] per bbk. 128t x 36o tile, 4x4/thread, K-chunk 64.
// grid 1024 = (bbk, ttile32), 288 thr
__global__ void k5_xdbl(const float* __restrict__ xpw){
    __shared__ float Xt[64][132];
    __shared__ float Wt[64][40];
    int bbk = blockIdx.x >> 5, tile = blockIdx.x & 31;
    int bb = bbk >> 2, k = bbk & 3, tid = threadIdx.x;
    int t0 = tile*128;
    int us; const float* ub = u_base(bb, k, t0, us);
    int ct = tid % 9, rt = tid / 9;
    float acc[4][4];
    #pragma unroll
    for (int i=0;i<4;i++)
        #pragma unroll
        for (int j=0;j<4;j++) acc[i][j]=0.f;
    #pragma unroll
    for (int kc=0; kc<2; kc++){
        for (int idx=tid; idx<8192; idx+=288){
            int tl = idx >> 6, c = idx & 63;
            Xt[c][tl] = ub[(long)tl*us + kc*64 + c];
        }
        for (int idx=tid; idx<2304; idx+=288){
            int o = idx >> 6, c = idx & 63;
            Wt[c][o] = xpw[(k*36+o)*128 + kc*64 + c];
        }
        __syncthreads();
        #pragma unroll 4
        for (int c=0;c<64;c++){
            float4 xv = *(const float4*)&Xt[c][rt*4];
            float4 wv = *(const float4*)&Wt[c][ct*4];
            float xr[4] = {xv.x,xv.y,xv.z,xv.w};
            float wr[4] = {wv.x,wv.y,wv.z,wv.w};
            #pragma unroll
            for (int i=0;i<4;i++)
                #pragma unroll
                for (int j=0;j<4;j++) acc[i][j] = fmaf(xr[i], wr[j], acc[i][j]);
        }
        __syncthreads();
    }
    if (ct == 0){
        #pragma unroll
        for (int i=0;i<4;i++){
            float4 v = make_float4(acc[i][0],acc[i][1],acc[i][2],acc[i][3]);
            *(float4*)&g_dts[((size_t)bbk*4096 + t0 + rt*4 + i)*4] = v;
        }
    } else {
        #pragma unroll
        for (int i=0;i<4;i++){
            float4 v = make_float4(acc[i][0],acc[i][1],acc[i][2],acc[i][3]);
            *(float4*)&g_bc[((size_t)bbk*4096 + t0 + rt*4 + i)*32 + (ct-1)*4] = v;
        }
    }
}

// K5b: delta = softplus(dts . dt_w + dt_b). grid (32,64), 256 thr
__global__ void k5b_delta(const float* __restrict__ dtw, const float* __restrict__ dtb){
    __shared__ float sdts[64][4];
    int bbk = blockIdx.x, k = bbk & 3;
    int t0 = blockIdx.y*64;
    int d = threadIdx.x & 127, sub = threadIdx.x >> 7;
    if (threadIdx.x < 256)
        ((float*)sdts)[threadIdx.x] = g_dts[((size_t)bbk*4096 + t0)*4 + threadIdx.x];
    __syncthreads();
    float4 wv = *(const float4*)(dtw + (k*128+d)*4);
    float bv = dtb[k*128+d];
    float* dst = g_del + ((size_t)bbk*4096 + t0 + sub*32)*128 + d;
    #pragma unroll 4
    for (int tl=0; tl<32; tl++){
        float4 q = *(const float4*)sdts[sub*32 + tl];
        float xx = q.x*wv.x + q.y*wv.y + q.z*wv.z + q.w*wv.w + bv;
        float sp = (xx > 20.f) ? xx : log1pf(__expf(xx));
        dst[(size_t)tl*128] = sp;
    }
}

// K6a: pass1 chunk-local scan (128 steps). warp=(bbk,dg,chunk32). grid 2048, 256 thr
__global__ void k6a_scan1(){
    int gw = blockIdx.x*8 + (threadIdx.x >> 5);
    int lane = threadIdx.x & 31;
    int chunk = gw & 31, dg = (gw >> 5) & 15, bbk = gw >> 9;
    int bb = bbk >> 2, k = bbk & 3;
    int dl = lane >> 2, sg = lane & 3, d = dg*8 + dl;
    float4 Av = *(const float4*)(g_A + (size_t)(k*128+d)*16 + sg*4);
    float h0=0,h1=0,h2=0,h3=0, dsum=0;
    int t0 = chunk*128;
    const float* del = g_del + ((size_t)bbk*4096 + t0)*128 + d;
    const float* bc  = g_bc  + ((size_t)bbk*4096 + t0)*32 + sg*4;
    int us; const float* ub = u_base(bb, k, t0, us) + d;
    #pragma unroll 4
    for (int t=0; t<128; t++){
        float delta = del[(size_t)t*128];
        float uu = ub[(long)t*us];
        float4 B = *(const float4*)(bc + (size_t)t*32);
        float du = delta*uu;
        dsum += delta;
        float a0 = __expf(delta*Av.x), a1 = __expf(delta*Av.y);
        float a2 = __expf(delta*Av.z), a3 = __expf(delta*Av.w);
        h0 = fmaf(a0,h0,du*B.x); h1 = fmaf(a1,h1,du*B.y);
        h2 = fmaf(a2,h2,du*B.z); h3 = fmaf(a3,h3,du*B.w);
    }
    size_t so = ((size_t)(bbk*32+chunk)*128 + d)*16 + sg*4;
    *(float4*)(g_hc + so) = make_float4(h0,h1,h2,h3);
    *(float4*)(g_cp + so) = make_float4(__expf(dsum*Av.x),__expf(dsum*Av.y),
                                        __expf(dsum*Av.z),__expf(dsum*Av.w));
}

// K6b: sequential scan over 32 chunk summaries. grid 256, 256 thr
__global__ void k6b_scan2(){
    int idx = blockIdx.x*256 + threadIdx.x;
    int bbk = idx >> 11, rem = idx & 2047;
    float H = 0.f;
    #pragma unroll
    for (int c=0; c<32; c++){
        size_t o = ((size_t)(bbk*32+c))*2048 + rem;
        g_hi[o] = H;
        H = g_cp[o]*H + g_hc[o];
    }
}

// K6c: pass3 with incoming state, emit y=C.h. grid 2048, 256 thr
__global__ void k6c_scan3(){
    int gw = blockIdx.x*8 + (threadIdx.x >> 5);
    int lane = threadIdx.x & 31;
    int chunk = gw & 31, dg = (gw >> 5) & 15, bbk = gw >> 9;
    int bb = bbk >> 2, k = bbk & 3;
    int dl = lane >> 2, sg = lane & 3, d = dg*8 + dl;
    float4 Av = *(const float4*)(g_A + (size_t)(k*128+d)*16 + sg*4);
    size_t so = ((size_t)(bbk*32+chunk)*128 + d)*16 + sg*4;
    float4 hi = *(const float4*)(g_hi + so);
    float h0=hi.x, h1=hi.y, h2=hi.z, h3=hi.w;
    int t0 = chunk*128;
    const float* del = g_del + ((size_t)bbk*4096 + t0)*128 + d;
    const float* bc  = g_bc  + ((size_t)bbk*4096 + t0)*32;
    int us; const float* ub = u_base(bb, k, t0, us) + d;
    float* yo = g_y4 + ((size_t)bbk*4096 + t0)*128 + d;
    #pragma unroll 4
    for (int t=0; t<128; t++){
        float delta = del[(size_t)t*128];
        float uu = ub[(long)t*us];
        float4 B = *(const float4*)(bc + (size_t)t*32 + sg*4);
        float4 C = *(const float4*)(bc + (size_t)t*32 + 16 + sg*4);
        float du = delta*uu;
        float a0 = __expf(delta*Av.x), a1 = __expf(delta*Av.y);
        float a2 = __expf(delta*Av.z), a3 = __expf(delta*Av.w);
        h0 = fmaf(a0,h0,du*B.x); h1 = fmaf(a1,h1,du*B.y);
        h2 = fmaf(a2,h2,du*B.z); h3 = fmaf(a3,h3,du*B.w);
        float acc = h0*C.x + h1*C.y + h2*C.z + h3*C.w;
        acc += __shfl_xor_sync(0xffffffffu, acc, 1);
        acc += __shfl_xor_sync(0xffffffffu, acc, 2);
        if (sg == 0) yo[(size_t)t*128] = acc;
    }
}

// K7: combine 4 dirs + Dsum*u + LN(128) + silu(z) gate. grid 4096, 256 thr
__global__ void k7_comb(const float* __restrict__ ong, const float* __restrict__ onb){
    int wid = threadIdx.x >> 5, lane = threadIdx.x & 31;
    int gp = blockIdx.x*8 + wid;
    int bb = gp >> 12, l = gp & 4095;
    const float* xr = g_xc2 + ((size_t)bb*4096 + l)*128;
    float v[4];
    #pragma unroll
    for (int i=0;i<4;i++){
        int dd = i*32 + lane;
        v[i] = g_dsum[dd]*xr[dd];
    }
    #pragma unroll
    for (int k=0;k<4;k++){
        int t = pos_map(k,l);
        const float* row = g_y4 + ((size_t)(bb*4+k)*4096 + t)*128;
        #pragma unroll
        for (int i=0;i<4;i++) v[i] += row[i*32+lane];
    }
    float s=0.f, ss=0.f;
    #pragma unroll
    for (int i=0;i<4;i++){ s += v[i]; ss += v[i]*v[i]; }
    #pragma unroll
    for (int o=16;o;o>>=1){ s += __shfl_xor_sync(0xffffffffu,s,o); ss += __shfl_xor_sync(0xffffffffu,ss,o); }
    float mu = s*(1.f/128.f);
    float rs = rsqrtf(ss*(1.f/128.f)-mu*mu+1e-5f);
    const float* zr = g_z + ((size_t)bb*4096+l)*128;
    float* gr = g_g + ((size_t)bb*4096+l)*128;
    #pragma unroll
    for (int i=0;i<4;i++){
        int dd = i*32+lane;
        float zz = zr[dd];
        float gate = zz/(1.f+__expf(-zz));
        gr[dd] = ((v[i]-mu)*rs*ong[dd]+onb[dd])*gate;
    }
}

// K8: out_proj [32768,128]x[128,64] + residual -> NCHW. 128x64 tile, 8x4/thread,
// K-chunk 32. grid 256, 256 thr
__global__ void k8_outproj(const float* __restrict__ opw, const float* __restrict__ scale){
    __shared__ float Xs[32][132];
    __shared__ float Ws[32][72];
    int row0 = blockIdx.x*128, tid = threadIdx.x;
    int ct = tid & 15, rt = tid >> 4;
    float acc[8][4];
    #pragma unroll
    for (int i=0;i<8;i++)
        #pragma unroll
        for (int j=0;j<4;j++) acc[i][j]=0.f;
    #pragma unroll
    for (int kc=0; kc<4; kc++){
        for (int idx=tid; idx<4096; idx+=256){
            int r = idx >> 5, c = idx & 31;
            Xs[c][r] = g_g[(size_t)(row0+r)*128 + kc*32 + c];
        }
        for (int idx=tid; idx<2048; idx+=256){
            int j = idx >> 5, c = idx & 31;
            Ws[c][j] = opw[j*128 + kc*32 + c];
        }
        __syncthreads();
        #pragma unroll 4
        for (int c=0;c<32;c++){
            float4 x0 = *(const float4*)&Xs[c][rt*4];
            float4 x1 = *(const float4*)&Xs[c][rt*4+64];
            float4 w0 = *(const float4*)&Ws[c][ct*4];
            float xr[8] = {x0.x,x0.y,x0.z,x0.w,x1.x,x1.y,x1.z,x1.w};
            float wr[4] = {w0.x,w0.y,w0.z,w0.w};
            #pragma unroll
            for (int i=0;i<8;i++)
                #pragma unroll
                for (int j=0;j<4;j++) acc[i][j] = fmaf(xr[i], wr[j], acc[i][j]);
        }
        __syncthreads();
    }
    float s1 = scale[0] + 1.f;
    int bb = row0 >> 12, l0 = (row0 & 4095) + rt*4;
    #pragma unroll
    for (int jo=0;jo<4;jo++){
        int j = ct*4 + jo;
        int plane = (bb&3)*128 + (bb>>2)*64 + j;
        #pragma unroll
        for (int half=0; half<2; half++){
            int l = l0 + half*64;
            float4 xd4 = *(const float4*)(g_xd + (size_t)plane*4096 + l);
            float4 o4;
            o4.x = fmaf(s1, xd4.x, acc[half*4+0][jo]);
            o4.y = fmaf(s1, xd4.y, acc[half*4+1][jo]);
            o4.z = fmaf(s1, xd4.z, acc[half*4+2][jo]);
            o4.w = fmaf(s1, xd4.w, acc[half*4+3][jo]);
            *(float4*)(g_xo + (size_t)plane*4096 + l) = o4;
        }
    }
}

// K9: instance norm over HW + leaky relu. grid 512 planes, 256 thr
__global__ void k9_inorm(const float* __restrict__ gamma, const float* __restrict__ beta,
                         float* __restrict__ out){
    __shared__ float buf[4096];
    __shared__ float rsum[8], rsq[8];
    int plane = blockIdx.x, cch = plane & 127;
    const float* src = g_xo + (size_t)plane*4096;
    float s=0.f, ss=0.f;
    for (int idx=threadIdx.x; idx<1024; idx+=256){
        float4 v = ((const float4*)src)[idx];
        ((float4*)buf)[idx] = v;
        s += v.x+v.y+v.z+v.w;
        ss += v.x*v.x+v.y*v.y+v.z*v.z+v.w*v.w;
    }
    #pragma unroll
    for (int o=16;o;o>>=1){ s += __shfl_xor_sync(0xffffffffu,s,o); ss += __shfl_xor_sync(0xffffffffu,ss,o); }
    int wid = threadIdx.x >> 5;
    if ((threadIdx.x & 31) == 0){ rsum[wid]=s; rsq[wid]=ss; }
    __syncthreads();
    if (threadIdx.x == 0){
        float ts=0.f, tss=0.f;
        #pragma unroll
        for (int i=0;i<8;i++){ ts += rsum[i]; tss += rsq[i]; }
        float mu = ts*(1.f/4096.f);
        rsum[0] = mu;
        rsq[0]  = rsqrtf(tss*(1.f/4096.f)-mu*mu+1e-5f);
    }
    __syncthreads();
    float mu = rsum[0], rr = rsq[0];
    float gm = gamma[cch], bt = beta[cch];
    float* dst = out + (size_t)plane*4096;
    for (int idx=threadIdx.x; idx<4096; idx+=256){
        float v = (buf[idx]-mu)*rr*gm + bt;
        dst[idx] = v > 0.f ? v : 0.01f*v;
    }
}

extern "C" void kernel_launch(void* const* d_in, const int* in_sizes, int n_in,
                              void* d_out, int out_size) {
    const float* x        = (const float*)d_in[0];
    const float* dw_w     = (const float*)d_in[1];
    const float* dw_b     = (const float*)d_in[2];
    const float* scale    = (const float*)d_in[3];
    const float* ln1_g    = (const float*)d_in[4];
    const float* ln1_b    = (const float*)d_in[5];
    const float* in_proj  = (const float*)d_in[6];
    const float* conv_w   = (const float*)d_in[7];
    const float* conv_b   = (const float*)d_in[8];
    const float* x_proj   = (const float*)d_in[9];
    const float* dt_w     = (const float*)d_in[10];
    const float* dt_b     = (const float*)d_in[11];
    const float* A_logs   = (const float*)d_in[12];
    const float* Ds       = (const float*)d_in[13];
    const float* on_g     = (const float*)d_in[14];
    const float* on_b     = (const float*)d_in[15];
    const float* out_proj = (const float*)d_in[16];
    const float* in_gamma = (const float*)d_in[17];
    const float* in_beta  = (const float*)d_in[18];
    float* out = (float*)d_out;

    k0_prep    <<<32, 256>>>(A_logs, Ds);
    k1_dwconv  <<<2048, 256>>>(x, dw_w, dw_b);
    k2_ln      <<<512, 256>>>(ln1_g, ln1_b);
    k3_inproj  <<<dim3(256,2), 256>>>(in_proj);
    k4_conv    <<<1024, 256>>>(conv_w, conv_b);
    k4b_gather <<<dim3(8,128), 256>>>();
    k5_xdbl    <<<1024, 288>>>(x_proj);
    k5b_delta  <<<dim3(32,64), 256>>>(dt_w, dt_b);
    k6a_scan1  <<<2048, 256>>>();
    k6b_scan2  <<<256, 256>>>();
    k6c_scan3  <<<2048, 256>>>();
    k7_comb    <<<4096, 256>>>(on_g, on_b);
    k8_outproj <<<256, 256>>>(out_proj, scale);
    k9_inorm   <<<512, 256>>>(in_gamma, in_beta, out);
}

// round 6
// speedup vs baseline: 4.8029x; 1.1339x over previous
#include <cuda_runtime.h>
#include <cuda_bf16.h>

// B=4,C=128,H=W=64,L=4096, D=64, DI=128, N=16, R=4, K=4. bb=branch*4+b (8), bbk=bb*4+k (32)
// scan: 32 chunks x 128 steps

__device__ float g_xd  [4*128*4096];
__device__ float g_xln [8*4096*64];
__device__ float g_xc  [8*4096*128];
__device__ float g_z   [8*4096*128];
__device__ float g_xc2 [8*4096*128];
__device__ float g_u2  [8*4096*128];
__device__ float g_dts [32*4096*4];
__device__ float g_bc  [32*4096*32];
__device__ float g_hc  [32*32*128*16];
__device__ float g_cp  [32*32*128*16];
__device__ float g_hi  [32*32*128*16];
__device__ float g_y4  [32*4096*128];
__device__ float g_g   [8*4096*128];
__device__ float g_xo  [4*128*4096];
__device__ float g_A   [8192];
__device__ float g_dsum[128];

__device__ __forceinline__ int pos_map(int k, int t){
    int tt = (k >= 2) ? (4095 - t) : t;
    if (k & 1) tt = ((tt & 63) << 6) | (tt >> 6);
    return tt;
}

__device__ __forceinline__ const float* u_base(int bb, int k, int t0, int& us){
    const float* arr = (k & 1) ? g_u2 : g_xc2;
    int p0 = (k >= 2) ? (4095 - t0) : t0;
    us = (k >= 2) ? -128 : 128;
    return arr + ((size_t)bb*4096 + p0)*128;
}

__global__ void k0_prep(const float* __restrict__ A_logs, const float* __restrict__ Ds){
    int i = blockIdx.x*256 + threadIdx.x;
    if (i < 8192) g_A[i] = -expf(A_logs[i]);
    if (i < 128)  g_dsum[i] = Ds[i] + Ds[128+i] + Ds[256+i] + Ds[384+i];
}

// K1: depthwise 3x3 on x (NCHW), smem-tiled. grid 2048 = (plane, strip4), 256 thr
__global__ void k1_dwconv(const float* __restrict__ x, const float* __restrict__ w,
                          const float* __restrict__ b){
    int plane = blockIdx.x >> 2, strip = blockIdx.x & 3;
    int c = plane & 127, h0 = strip*16;
    __shared__ float t[18][64];
    const float* xp = x + (size_t)plane*4096;
    for (int i=threadIdx.x; i<1152; i+=256){
        int r = i >> 6, ww = i & 63, hh = h0-1+r;
        t[r][ww] = ((unsigned)hh < 64u) ? xp[hh*64+ww] : 0.f;
    }
    __syncthreads();
    float w9[9];
    #pragma unroll
    for (int i=0;i<9;i++) w9[i] = w[c*9+i];
    float bv = b[c];
    float* op = g_xd + (size_t)plane*4096 + h0*64;
    for (int i=threadIdx.x; i<1024; i+=256){
        int r = i >> 6, ww = i & 63;
        float acc = bv;
        #pragma unroll
        for (int dh=0; dh<3; dh++){
            #pragma unroll
            for (int dw=-1; dw<=1; dw++){
                int w2 = ww+dw;
                if ((unsigned)w2 < 64u) acc = fmaf(t[r+dh][w2], w9[dh*3+dw+1], acc);
            }
        }
        op[i] = acc;
    }
}

// K2: NCHW -> pixel-major + LayerNorm(64). grid 512 = (bb,h), 256 thr
__global__ void k2_ln(const float* __restrict__ g1, const float* __restrict__ b1){
    int bb = blockIdx.x >> 6, h = blockIdx.x & 63;
    int br = bb >> 2, bi = bb & 3;
    __shared__ float tile[64][65];
    __shared__ float smu[64], srs[64];
    const float* src = g_xd + (size_t)(bi*128 + br*64)*4096 + h*64;
    for (int idx=threadIdx.x; idx<4096; idx+=256){
        int c = idx >> 6, w = idx & 63;
        tile[w][c] = src[(size_t)c*4096 + w];
    }
    __syncthreads();
    if (threadIdx.x < 64){
        int w = threadIdx.x; float s=0.f, ss=0.f;
        #pragma unroll 8
        for (int c=0;c<64;c++){ float v=tile[w][c]; s+=v; ss+=v*v; }
        float mu = s*(1.f/64.f);
        smu[w]=mu; srs[w]=rsqrtf(ss*(1.f/64.f)-mu*mu+1e-5f);
    }
    __syncthreads();
    float* dst = g_xln + ((size_t)bb*4096 + h*64)*64;
    for (int idx=threadIdx.x; idx<4096; idx+=256){
        int w = idx >> 6, c = idx & 63;
        dst[idx] = (tile[w][c]-smu[w])*srs[w]*g1[c] + b1[c];
    }
}

// K3: in_proj GEMM [32768,64]x[64,256], 64x128 tile, 4x8/thread, K-chunk 32.
// grid (512,2), 256 thr
__global__ void k3_inproj(const float* __restrict__ ipw){
    __shared__ float As[32][68];
    __shared__ float Ws[32][132];
    int row0 = blockIdx.x*64, jh = blockIdx.y, tid = threadIdx.x;
    int ct = tid & 15, rt = tid >> 4;
    float acc[4][8];
    #pragma unroll
    for (int i=0;i<4;i++)
        #pragma unroll
        for (int j=0;j<8;j++) acc[i][j]=0.f;
    #pragma unroll
    for (int kc=0; kc<2; kc++){
        for (int idx=tid; idx<2048; idx+=256){
            int r = idx >> 5, c = idx & 31;
            As[c][r] = g_xln[(size_t)(row0+r)*64 + kc*32 + c];
        }
        for (int idx=tid; idx<4096; idx+=256){
            int j = idx >> 5, c = idx & 31;
            Ws[c][j] = ipw[(jh*128+j)*64 + kc*32 + c];
        }
        __syncthreads();
        #pragma unroll 8
        for (int c=0;c<32;c++){
            float4 a0 = *(const float4*)&As[c][rt*4];
            float4 w0 = *(const float4*)&Ws[c][ct*4];
            float4 w1 = *(const float4*)&Ws[c][64+ct*4];
            float ar[4] = {a0.x,a0.y,a0.z,a0.w};
            float wr[8] = {w0.x,w0.y,w0.z,w0.w,w1.x,w1.y,w1.z,w1.w};
            #pragma unroll
            for (int i=0;i<4;i++)
                #pragma unroll
                for (int j=0;j<8;j++) acc[i][j] = fmaf(ar[i], wr[j], acc[i][j]);
        }
        __syncthreads();
    }
    float* dstbase = (jh==0) ? g_xc : g_z;
    #pragma unroll
    for (int i=0;i<4;i++){
        int r = row0 + rt*4 + i;
        *(float4*)&dstbase[(size_t)r*128 + ct*4] =
            make_float4(acc[i][0],acc[i][1],acc[i][2],acc[i][3]);
        *(float4*)&dstbase[(size_t)r*128 + 64 + ct*4] =
            make_float4(acc[i][4],acc[i][5],acc[i][6],acc[i][7]);
    }
}

// K4: depthwise 3x3 + SiLU on xc (pixel-major), smem-tiled by c-group.
// grid 1024 = (bb8, strip16, cg8), 256 thr
__global__ void k4_conv(const float* __restrict__ cw, const float* __restrict__ cb){
    int bb = blockIdx.x >> 7;
    int strip = (blockIdx.x >> 3) & 15;
    int cg = blockIdx.x & 7;
    int h0 = strip*4, c0 = cg*16;
    __shared__ float t[6][64][16];
    const float* src = g_xc + (size_t)bb*4096*128 + c0;
    for (int i=threadIdx.x; i<6144; i+=256){
        int cl = i & 15, ww = (i>>4) & 63, r = i >> 10;
        int hh = h0-1+r;
        t[r][ww][cl] = ((unsigned)hh < 64u) ? src[(size_t)(hh*64+ww)*128 + cl] : 0.f;
    }
    __syncthreads();
    int cl = threadIdx.x & 15, c = c0 + cl;
    float w9[9];
    #pragma unroll
    for (int i=0;i<9;i++) w9[i] = cw[c*9+i];
    float bv = cb[c];
    float* dst = g_xc2 + (size_t)bb*4096*128 + c0 + cl;
    for (int i=threadIdx.x; i<4096; i+=256){
        int ww = (i>>4) & 63, r = i >> 10;
        float acc = bv;
        #pragma unroll
        for (int dh=0; dh<3; dh++){
            #pragma unroll
            for (int dw=-1; dw<=1; dw++){
                int w2 = ww+dw;
                if ((unsigned)w2 < 64u) acc = fmaf(t[r+dh][w2][cl], w9[dh*3+dw+1], acc);
            }
        }
        acc = acc/(1.f+__expf(-acc));
        dst[(size_t)((h0+r)*64+ww)*128] = acc;
    }
}

// K4b: materialize transpose order. grid (8,128), 256 thr
__global__ void k4b_gather(){
    int bb = blockIdx.x, tb = blockIdx.y*32;
    int c = threadIdx.x & 127, tl = threadIdx.x >> 7;
    #pragma unroll
    for (int i=0;i<16;i++){
        int t = tb + i*2 + tl;
        int p = ((t & 63) << 6) | (t >> 6);
        g_u2[((size_t)bb*4096 + t)*128 + c] = g_xc2[((size_t)bb*4096 + p)*128 + c];
    }
}

// K5: x_proj [4096,128]x[128,36] per bbk. 128t x 36o tile, 4x4/thread, K-chunk 64.
// grid 1024 = (bbk, ttile32), 288 thr
__global__ void k5_xdbl(const float* __restrict__ xpw){
    __shared__ float Xt[64][132];
    __shared__ float Wt[64][40];
    int bbk = blockIdx.x >> 5, tile = blockIdx.x & 31;
    int bb = bbk >> 2, k = bbk & 3, tid = threadIdx.x;
    int t0 = tile*128;
    int us; const float* ub = u_base(bb, k, t0, us);
    int ct = tid % 9, rt = tid / 9;
    float acc[4][4];
    #pragma unroll
    for (int i=0;i<4;i++)
        #pragma unroll
        for (int j=0;j<4;j++) acc[i][j]=0.f;
    #pragma unroll
    for (int kc=0; kc<2; kc++){
        for (int idx=tid; idx<8192; idx+=288){
            int tl = idx >> 6, c = idx & 63;
            Xt[c][tl] = ub[(long)tl*us + kc*64 + c];
        }
        for (int idx=tid; idx<2304; idx+=288){
            int o = idx >> 6, c = idx & 63;
            Wt[c][o] = xpw[(k*36+o)*128 + kc*64 + c];
        }
        __syncthreads();
        #pragma unroll 4
        for (int c=0;c<64;c++){
            float4 xv = *(const float4*)&Xt[c][rt*4];
            float4 wv = *(const float4*)&Wt[c][ct*4];
            float xr[4] = {xv.x,xv.y,xv.z,xv.w};
            float wr[4] = {wv.x,wv.y,wv.z,wv.w};
            #pragma unroll
            for (int i=0;i<4;i++)
                #pragma unroll
                for (int j=0;j<4;j++) acc[i][j] = fmaf(xr[i], wr[j], acc[i][j]);
        }
        __syncthreads();
    }
    if (ct == 0){
        #pragma unroll
        for (int i=0;i<4;i++){
            float4 v = make_float4(acc[i][0],acc[i][1],acc[i][2],acc[i][3]);
            *(float4*)&g_dts[((size_t)bbk*4096 + t0 + rt*4 + i)*4] = v;
        }
    } else {
        #pragma unroll
        for (int i=0;i<4;i++){
            float4 v = make_float4(acc[i][0],acc[i][1],acc[i][2],acc[i][3]);
            *(float4*)&g_bc[((size_t)bbk*4096 + t0 + rt*4 + i)*32 + (ct-1)*4] = v;
        }
    }
}

// K6a: pass1 chunk-local scan (128 steps), delta computed in-warp.
// warp=(bbk,dg,chunk32). grid 2048, 256 thr
__global__ void k6a_scan1(const float* __restrict__ dtw, const float* __restrict__ dtb){
    int gw = blockIdx.x*8 + (threadIdx.x >> 5);
    int lane = threadIdx.x & 31;
    int chunk = gw & 31, dg = (gw >> 5) & 15, bbk = gw >> 9;
    int bb = bbk >> 2, k = bbk & 3;
    int dl = lane >> 2, sg = lane & 3, d = dg*8 + dl;
    float4 Av = *(const float4*)(g_A + (size_t)(k*128+d)*16 + sg*4);
    float4 wv = *(const float4*)(dtw + (k*128+d)*4);
    float bvb = dtb[k*128+d];
    float h0=0,h1=0,h2=0,h3=0, dsum=0;
    int t0 = chunk*128;
    const float4* dts4 = (const float4*)(g_dts + ((size_t)bbk*4096 + t0)*4);
    const float* bc  = g_bc  + ((size_t)bbk*4096 + t0)*32 + sg*4;
    int us; const float* ub = u_base(bb, k, t0, us) + d;
    for (int g4=0; g4<32; g4++){
        float4 q = dts4[g4*4 + sg];
        float xx = q.x*wv.x + q.y*wv.y + q.z*wv.z + q.w*wv.w + bvb;
        float sp = (xx > 20.f) ? xx : log1pf(__expf(xx));
        #pragma unroll
        for (int j=0;j<4;j++){
            int t = g4*4 + j;
            float delta = __shfl_sync(0xffffffffu, sp, j, 4);
            float uu = ub[(long)t*us];
            float4 B = *(const float4*)(bc + (size_t)t*32);
            float du = delta*uu;
            dsum += delta;
            float a0 = __expf(delta*Av.x), a1 = __expf(delta*Av.y);
            float a2 = __expf(delta*Av.z), a3 = __expf(delta*Av.w);
            h0 = fmaf(a0,h0,du*B.x); h1 = fmaf(a1,h1,du*B.y);
            h2 = fmaf(a2,h2,du*B.z); h3 = fmaf(a3,h3,du*B.w);
        }
    }
    size_t so = ((size_t)(bbk*32+chunk)*128 + d)*16 + sg*4;
    *(float4*)(g_hc + so) = make_float4(h0,h1,h2,h3);
    *(float4*)(g_cp + so) = make_float4(__expf(dsum*Av.x),__expf(dsum*Av.y),
                                        __expf(dsum*Av.z),__expf(dsum*Av.w));
}

// K6b: sequential scan over 32 chunk summaries. grid 256, 256 thr
__global__ void k6b_scan2(){
    int idx = blockIdx.x*256 + threadIdx.x;
    int bbk = idx >> 11, rem = idx & 2047;
    float H = 0.f;
    #pragma unroll
    for (int c=0; c<32; c++){
        size_t o = ((size_t)(bbk*32+c))*2048 + rem;
        g_hi[o] = H;
        H = g_cp[o]*H + g_hc[o];
    }
}

// K6c: pass3 with incoming state, emit y=C.h, delta in-warp. grid 2048, 256 thr
__global__ void k6c_scan3(const float* __restrict__ dtw, const float* __restrict__ dtb){
    int gw = blockIdx.x*8 + (threadIdx.x >> 5);
    int lane = threadIdx.x & 31;
    int chunk = gw & 31, dg = (gw >> 5) & 15, bbk = gw >> 9;
    int bb = bbk >> 2, k = bbk & 3;
    int dl = lane >> 2, sg = lane & 3, d = dg*8 + dl;
    float4 Av = *(const float4*)(g_A + (size_t)(k*128+d)*16 + sg*4);
    float4 wv = *(const float4*)(dtw + (k*128+d)*4);
    float bvb = dtb[k*128+d];
    size_t so = ((size_t)(bbk*32+chunk)*128 + d)*16 + sg*4;
    float4 hi = *(const float4*)(g_hi + so);
    float h0=hi.x, h1=hi.y, h2=hi.z, h3=hi.w;
    int t0 = chunk*128;
    const float4* dts4 = (const float4*)(g_dts + ((size_t)bbk*4096 + t0)*4);
    const float* bc  = g_bc  + ((size_t)bbk*4096 + t0)*32;
    int us; const float* ub = u_base(bb, k, t0, us) + d;
    float* yo = g_y4 + ((size_t)bbk*4096 + t0)*128 + d;
    for (int g4=0; g4<32; g4++){
        float4 q = dts4[g4*4 + sg];
        float xx = q.x*wv.x + q.y*wv.y + q.z*wv.z + q.w*wv.w + bvb;
        float sp = (xx > 20.f) ? xx : log1pf(__expf(xx));
        #pragma unroll
        for (int j=0;j<4;j++){
            int t = g4*4 + j;
            float delta = __shfl_sync(0xffffffffu, sp, j, 4);
            float uu = ub[(long)t*us];
            float4 B = *(const float4*)(bc + (size_t)t*32 + sg*4);
            float4 C = *(const float4*)(bc + (size_t)t*32 + 16 + sg*4);
            float du = delta*uu;
            float a0 = __expf(delta*Av.x), a1 = __expf(delta*Av.y);
            float a2 = __expf(delta*Av.z), a3 = __expf(delta*Av.w);
            h0 = fmaf(a0,h0,du*B.x); h1 = fmaf(a1,h1,du*B.y);
            h2 = fmaf(a2,h2,du*B.z); h3 = fmaf(a3,h3,du*B.w);
            float acc = h0*C.x + h1*C.y + h2*C.z + h3*C.w;
            acc += __shfl_xor_sync(0xffffffffu, acc, 1);
            acc += __shfl_xor_sync(0xffffffffu, acc, 2);
            if (sg == 0) yo[(size_t)t*128] = acc;
        }
    }
}

// K7: combine 4 dirs + Dsum*u + LN(128) + silu(z) gate. grid 4096, 256 thr
__global__ void k7_comb(const float* __restrict__ ong, const float* __restrict__ onb){
    int wid = threadIdx.x >> 5, lane = threadIdx.x & 31;
    int gp = blockIdx.x*8 + wid;
    int bb = gp >> 12, l = gp & 4095;
    const float* xr = g_xc2 + ((size_t)bb*4096 + l)*128;
    float v[4];
    #pragma unroll
    for (int i=0;i<4;i++){
        int dd = i*32 + lane;
        v[i] = g_dsum[dd]*xr[dd];
    }
    #pragma unroll
    for (int k=0;k<4;k++){
        int t = pos_map(k,l);
        const float* row = g_y4 + ((size_t)(bb*4+k)*4096 + t)*128;
        #pragma unroll
        for (int i=0;i<4;i++) v[i] += row[i*32+lane];
    }
    float s=0.f, ss=0.f;
    #pragma unroll
    for (int i=0;i<4;i++){ s += v[i]; ss += v[i]*v[i]; }
    #pragma unroll
    for (int o=16;o;o>>=1){ s += __shfl_xor_sync(0xffffffffu,s,o); ss += __shfl_xor_sync(0xffffffffu,ss,o); }
    float mu = s*(1.f/128.f);
    float rs = rsqrtf(ss*(1.f/128.f)-mu*mu+1e-5f);
    const float* zr = g_z + ((size_t)bb*4096+l)*128;
    float* gr = g_g + ((size_t)bb*4096+l)*128;
    #pragma unroll
    for (int i=0;i<4;i++){
        int dd = i*32+lane;
        float zz = zr[dd];
        float gate = zz/(1.f+__expf(-zz));
        gr[dd] = ((v[i]-mu)*rs*ong[dd]+onb[dd])*gate;
    }
}

// K8: out_proj [32768,128]x[128,64] + residual -> NCHW. 128x64 tile, 8x4/thread,
// K-chunk 32. grid 256, 256 thr
__global__ void k8_outproj(const float* __restrict__ opw, const float* __restrict__ scale){
    __shared__ float Xs[32][132];
    __shared__ float Ws[32][72];
    int row0 = blockIdx.x*128, tid = threadIdx.x;
    int ct = tid & 15, rt = tid >> 4;
    float acc[8][4];
    #pragma unroll
    for (int i=0;i<8;i++)
        #pragma unroll
        for (int j=0;j<4;j++) acc[i][j]=0.f;
    #pragma unroll
    for (int kc=0; kc<4; kc++){
        for (int idx=tid; idx<4096; idx+=256){
            int r = idx >> 5, c = idx & 31;
            Xs[c][r] = g_g[(size_t)(row0+r)*128 + kc*32 + c];
        }
        for (int idx=tid; idx<2048; idx+=256){
            int j = idx >> 5, c = idx & 31;
            Ws[c][j] = opw[j*128 + kc*32 + c];
        }
        __syncthreads();
        #pragma unroll 4
        for (int c=0;c<32;c++){
            float4 x0 = *(const float4*)&Xs[c][rt*4];
            float4 x1 = *(const float4*)&Xs[c][rt*4+64];
            float4 w0 = *(const float4*)&Ws[c][ct*4];
            float xr[8] = {x0.x,x0.y,x0.z,x0.w,x1.x,x1.y,x1.z,x1.w};
            float wr[4] = {w0.x,w0.y,w0.z,w0.w};
            #pragma unroll
            for (int i=0;i<8;i++)
                #pragma unroll
                for (int j=0;j<4;j++) acc[i][j] = fmaf(xr[i], wr[j], acc[i][j]);
        }
        __syncthreads();
    }
    float s1 = scale[0] + 1.f;
    int bb = row0 >> 12, l0 = (row0 & 4095) + rt*4;
    #pragma unroll
    for (int jo=0;jo<4;jo++){
        int j = ct*4 + jo;
        int plane = (bb&3)*128 + (bb>>2)*64 + j;
        #pragma unroll
        for (int half=0; half<2; half++){
            int l = l0 + half*64;
            float4 xd4 = *(const float4*)(g_xd + (size_t)plane*4096 + l);
            float4 o4;
            o4.x = fmaf(s1, xd4.x, acc[half*4+0][jo]);
            o4.y = fmaf(s1, xd4.y, acc[half*4+1][jo]);
            o4.z = fmaf(s1, xd4.z, acc[half*4+2][jo]);
            o4.w = fmaf(s1, xd4.w, acc[half*4+3][jo]);
            *(float4*)(g_xo + (size_t)plane*4096 + l) = o4;
        }
    }
}

// K9: instance norm over HW + leaky relu. grid 512 planes, 256 thr
__global__ void k9_inorm(const float* __restrict__ gamma, const float* __restrict__ beta,
                         float* __restrict__ out){
    __shared__ float buf[4096];
    __shared__ float rsum[8], rsq[8];
    int plane = blockIdx.x, cch = plane & 127;
    const float* src = g_xo + (size_t)plane*4096;
    float s=0.f, ss=0.f;
    for (int idx=threadIdx.x; idx<1024; idx+=256){
        float4 v = ((const float4*)src)[idx];
        ((float4*)buf)[idx] = v;
        s += v.x+v.y+v.z+v.w;
        ss += v.x*v.x+v.y*v.y+v.z*v.z+v.w*v.w;
    }
    #pragma unroll
    for (int o=16;o;o>>=1){ s += __shfl_xor_sync(0xffffffffu,s,o); ss += __shfl_xor_sync(0xffffffffu,ss,o); }
    int wid = threadIdx.x >> 5;
    if ((threadIdx.x & 31) == 0){ rsum[wid]=s; rsq[wid]=ss; }
    __syncthreads();
    if (threadIdx.x == 0){
        float ts=0.f, tss=0.f;
        #pragma unroll
        for (int i=0;i<8;i++){ ts += rsum[i]; tss += rsq[i]; }
        float mu = ts*(1.f/4096.f);
        rsum[0] = mu;
        rsq[0]  = rsqrtf(tss*(1.f/4096.f)-mu*mu+1e-5f);
    }
    __syncthreads();
    float mu = rsum[0], rr = rsq[0];
    float gm = gamma[cch], bt = beta[cch];
    float* dst = out + (size_t)plane*4096;
    for (int idx=threadIdx.x; idx<4096; idx+=256){
        float v = (buf[idx]-mu)*rr*gm + bt;
        dst[idx] = v > 0.f ? v : 0.01f*v;
    }
}

extern "C" void kernel_launch(void* const* d_in, const int* in_sizes, int n_in,
                              void* d_out, int out_size) {
    const float* x        = (const float*)d_in[0];
    const float* dw_w     = (const float*)d_in[1];
    const float* dw_b     = (const float*)d_in[2];
    const float* scale    = (const float*)d_in[3];
    const float* ln1_g    = (const float*)d_in[4];
    const float* ln1_b    = (const float*)d_in[5];
    const float* in_proj  = (const float*)d_in[6];
    const float* conv_w   = (const float*)d_in[7];
    const float* conv_b   = (const float*)d_in[8];
    const float* x_proj   = (const float*)d_in[9];
    const float* dt_w     = (const float*)d_in[10];
    const float* dt_b     = (const float*)d_in[11];
    const float* A_logs   = (const float*)d_in[12];
    const float* Ds       = (const float*)d_in[13];
    const float* on_g     = (const float*)d_in[14];
    const float* on_b     = (const float*)d_in[15];
    const float* out_proj = (const float*)d_in[16];
    const float* in_gamma = (const float*)d_in[17];
    const float* in_beta  = (const float*)d_in[18];
    float* out = (float*)d_out;

    k0_prep    <<<32, 256>>>(A_logs, Ds);
    k1_dwconv  <<<2048, 256>>>(x, dw_w, dw_b);
    k2_ln      <<<512, 256>>>(ln1_g, ln1_b);
    k3_inproj  <<<dim3(512,2), 256>>>(in_proj);
    k4_conv    <<<1024, 256>>>(conv_w, conv_b);
    k4b_gather <<<dim3(8,128), 256>>>();
    k5_xdbl    <<<1024, 288>>>(x_proj);
    k6a_scan1  <<<2048, 256>>>(dt_w, dt_b);
    k6b_scan2  <<<256, 256>>>();
    k6c_scan3  <<<2048, 256>>>(dt_w, dt_b);
    k7_comb    <<<4096, 256>>>(on_g, on_b);
    k8_outproj <<<256, 256>>>(out_proj, scale);
    k9_inorm   <<<512, 256>>>(in_gamma, in_beta, out);
}